// round 6
// baseline (speedup 1.0000x reference)
#include <cuda_runtime.h>
#include <cuda_fp16.h>
#include <cstdint>

#define DIM  1024
#define NTOK 4096
#define NSK  50
#define BM 128
#define BN 256
#define BK 64                             // 64 halves = 128B row
#define NSTAGE 4
#define EPC 5                             // experts per CTA (phase 1 chaining)
#define A_BYTES (BM*128)                  // 16KB per stage
#define B_BYTES (BN*128)                  // 32KB per stage
#define SMEM_DYN (NSTAGE*(A_BYTES+B_BYTES) + 1024)   // 197632

// ---------------- scratch (static device, allocation-free) ----------------
__device__ __half g_Xh [(size_t)NTOK*DIM];
__device__ __half g_W1h[(size_t)NSK*DIM*DIM];        // transposed: [e][h][d]
__device__ __half g_W2h[(size_t)NSK*DIM*DIM];        // transposed: [e][d][h]
__device__ __half g_Hh [(size_t)NSK*NTOK*DIM];       // gate-scaled hidden
__device__ float  g_gates[(size_t)NTOK*NSK];

// ---------------- helpers ----------------
__device__ __forceinline__ uint32_t smem_u32(const void* p){
    uint32_t a; asm("{ .reg .u64 t; cvta.to.shared.u64 t, %1; cvt.u32.u64 %0, t; }":"=r"(a):"l"(p)); return a;
}
__device__ __forceinline__ void cp_async16(uint32_t s, const void* gp){
    uint64_t g = __cvta_generic_to_global(gp);
    asm volatile("cp.async.cg.shared.global [%0], [%1], 16;"::"r"(s),"l"(g));
}
#define CP_COMMIT() asm volatile("cp.async.commit_group;":::"memory")

#define LDSM_X4(r, a) \
    asm volatile("ldmatrix.sync.aligned.m8n8.x4.shared.b16 {%0,%1,%2,%3}, [%4];" \
        : "=r"((r)[0]),"=r"((r)[1]),"=r"((r)[2]),"=r"((r)[3]) : "r"(a))

#define MMA_F16(c, a, b0, b1) \
    asm volatile("mma.sync.aligned.m16n8k16.row.col.f32.f16.f16.f32 " \
        "{%0,%1,%2,%3},{%4,%5,%6,%7},{%8,%9},{%0,%1,%2,%3};" \
        : "+f"((c)[0]),"+f"((c)[1]),"+f"((c)[2]),"+f"((c)[3]) \
        : "r"((a)[0]),"r"((a)[1]),"r"((a)[2]),"r"((a)[3]),"r"(b0),"r"(b1))

// ---------------- prep kernels ----------------
// gates + x half-conversion fused (both read the same x row)
__global__ void gates_kernel(const float* __restrict__ x, const float* __restrict__ Wg,
                             const float* __restrict__ bg){
    int n = blockIdx.x, tid = threadIdx.x;
    __shared__ float xs[DIM]; __shared__ float raw[64]; __shared__ float ssum;
    for(int j=tid; j<DIM; j+=128){
        float v = x[(size_t)n*DIM + j];
        xs[j] = v;
        g_Xh[(size_t)n*DIM + j] = __float2half_rn(v);
    }
    __syncthreads();
    int wid = tid>>5, lid = tid&31;
    for(int s=wid; s<NSK; s+=4){
        float acc = 0.f;
        for(int j=lid; j<DIM; j+=32) acc += xs[j]*Wg[(size_t)j*NSK + s];
        #pragma unroll
        for(int o=16;o;o>>=1) acc += __shfl_xor_sync(0xFFFFFFFFu, acc, o);
        if(lid==0) raw[s] = acc + bg[s];
    }
    __syncthreads();
    if(tid==0){
        float m = -1e30f;
        for(int s=0;s<NSK;s++) m = fmaxf(m, raw[s]);
        float sm = 0.f;
        for(int s=0;s<NSK;s++){ float e = __expf(raw[s]-m); raw[s]=e; sm+=e; }
        ssum = sm;
    }
    __syncthreads();
    if(tid<NSK) g_gates[(size_t)n*NSK + tid] = raw[tid]/ssum;
}

// out[e][j][i] = half(in[e][i][j]); which: 0->g_W1h, 1->g_W2h
__global__ void transpose_round_kernel(const float* __restrict__ in, int which){
    __shared__ float tile[32][33];
    __half* out = which ? g_W2h : g_W1h;
    size_t base = (size_t)blockIdx.z*DIM*DIM;
    int i0 = blockIdx.y*32, j0 = blockIdx.x*32, tx = threadIdx.x;
    #pragma unroll
    for(int r=threadIdx.y; r<32; r+=8)
        tile[r][tx] = in[base + (size_t)(i0+r)*DIM + j0 + tx];
    __syncthreads();
    #pragma unroll
    for(int r=threadIdx.y; r<32; r+=8)
        out[base + (size_t)(j0+r)*DIM + i0 + tx] = __float2half_rn(tile[tx][r]);
}

// out[n,d] = sum_e gates[n,e]*b2[e,d]
__global__ void biasinit_kernel(const float* __restrict__ b2, float* __restrict__ out){
    __shared__ float gs[32][52]; __shared__ float bs[NSK][128];
    int t0 = blockIdx.x*32, d0 = blockIdx.y*128, tid = threadIdx.x;
    for(int i=tid; i<32*NSK; i+=256){ int r=i/NSK, e=i%NSK; gs[r][e] = g_gates[(size_t)(t0+r)*NSK + e]; }
    for(int i=tid; i<NSK*128; i+=256){ int e=i>>7, c=i&127; bs[e][c] = b2[(size_t)e*DIM + d0 + c]; }
    __syncthreads();
    int c = tid&127, rb = tid>>7;
    for(int k=0;k<16;k++){
        int r = rb + k*2;
        float acc = 0.f;
        #pragma unroll
        for(int e=0;e<NSK;e++) acc += gs[r][e]*bs[e][c];
        out[(size_t)(t0+r)*DIM + d0 + c] = acc;
    }
}

// ---------------- main fp16 mma.sync GEMM ----------------
// 8 warps, warp grid 2x4, warp tile 64x64.
// PHASE 1: grid (32,4,10); each CTA chains EPC=5 experts as one continuous
//          pipeline (NS=80 steps), per-expert register epilogue:
//          Hh[e][m][h] = half( gates[m][e]*relu( Xh @ W1h[e]^T + b1[e] ) )
// PHASE 2: out[m][d] += Hh_all @ W2h_all^T over K=51200, grid (32,4)
template<int PHASE>
__global__ void __launch_bounds__(256,1) gemm_kernel(const float* __restrict__ b1,
                                                     float* __restrict__ dout){
    extern __shared__ char dsm[];
    const uint32_t sb = (smem_u32(dsm) + 1023u) & ~1023u;
    const uint32_t A0 = sb, B0 = sb + NSTAGE*A_BYTES;
    const int tid = threadIdx.x, wid = tid>>5, lane = tid&31;
    const int wm = wid & 1, wn = wid >> 1;            // 2x4 warp grid
    const int m0 = blockIdx.x*BM, n0 = blockIdx.y*BN;
    const int NS = (PHASE==1) ? (EPC*DIM/BK) : (NSK*DIM/BK);   // 80 / 800

    // ldmatrix per-lane addressing (SW128: 16B chunk ^= (row&7)<<4)
    const int mat = lane>>3, rr = lane&7;
    const int a_rowl = (mat&1)*8 + rr;
    const int a_bc   = (mat>>1)*16;
    const int b_nl   = (mat>>1)*8 + rr;
    const int b_bc   = (mat&1)*16;
    const uint32_t xorv = (uint32_t)(rr<<4);

    float c[4][8][4];
    #pragma unroll
    for(int i=0;i<4;i++)
      #pragma unroll
      for(int j=0;j<8;j++)
        #pragma unroll
        for(int k=0;k<4;k++) c[i][j][k] = 0.f;

    const int gr = lane>>2, gc = (lane&3)*2;

    auto load_tile = [&](int step){
        const __half *Ag, *Bg;
        if(PHASE==1){
            int e = blockIdx.z*EPC + (step>>4), kk = (step&15)*BK;
            Ag = g_Xh  + (size_t)m0*DIM + kk;
            Bg = g_W1h + ((size_t)e*DIM + n0)*DIM + kk;
        } else {
            int e = step>>4, kk = (step&15)*BK;
            Ag = g_Hh  + ((size_t)e*NTOK + m0)*DIM + kk;
            Bg = g_W2h + ((size_t)e*DIM + n0)*DIM + kk;
        }
        uint32_t as = A0 + (step&3)*A_BYTES, bs = B0 + (step&3)*B_BYTES;
        #pragma unroll
        for(int i=0;i<4;i++){ int q = tid + i*256; int r=q>>3, cc=q&7;
            cp_async16(as + (uint32_t)(r*128 + ((cc*16) ^ ((r&7)<<4))), Ag + (size_t)r*DIM + cc*8); }
        #pragma unroll
        for(int i=0;i<8;i++){ int q = tid + i*256; int r=q>>3, cc=q&7;
            cp_async16(bs + (uint32_t)(r*128 + ((cc*16) ^ ((r&7)<<4))), Bg + (size_t)r*DIM + cc*8); }
        CP_COMMIT();
    };

    // phase-1 per-expert epilogue (registers -> gmem, smem untouched)
    auto epilogue1 = [&](int e){
        #pragma unroll
        for(int mi=0; mi<4; mi++){
            int r0 = m0 + wm*64 + mi*16 + gr;
            #pragma unroll
            for(int half=0; half<2; half++){
                int row = r0 + half*8;
                float gate = g_gates[(size_t)row*NSK + e];
                #pragma unroll
                for(int ni=0; ni<8; ni++){
                    int col = n0 + wn*64 + ni*8 + gc;
                    const float2 bb = *(const float2*)(b1 + (size_t)e*DIM + col);
                    float o0 = fmaxf(c[mi][ni][half*2+0] + bb.x, 0.f)*gate;
                    float o1 = fmaxf(c[mi][ni][half*2+1] + bb.y, 0.f)*gate;
                    *(__half2*)(g_Hh + ((size_t)e*NTOK + row)*DIM + col) =
                        __floats2half2_rn(o0, o1);
                    c[mi][ni][half*2+0] = 0.f;
                    c[mi][ni][half*2+1] = 0.f;
                }
            }
        }
    };

    load_tile(0); load_tile(1); load_tile(2);

    for(int step=0; step<NS; step++){
        asm volatile("cp.async.wait_group 2;":::"memory");
        __syncthreads();
        if(step+3 < NS) load_tile(step+3); else CP_COMMIT();

        const uint32_t as = A0 + (step&3)*A_BYTES;
        const uint32_t bs = B0 + (step&3)*B_BYTES;
        #pragma unroll
        for(int ks=0; ks<4; ks++){
            uint32_t a[4][4], b[4][4];
            #pragma unroll
            for(int mi=0; mi<4; mi++){
                int row = wm*64 + mi*16 + a_rowl;
                LDSM_X4(a[mi], as + (uint32_t)(row*128) + (((uint32_t)(ks*32 + a_bc)) ^ xorv));
            }
            #pragma unroll
            for(int p=0; p<4; p++){
                int n = wn*64 + p*16 + b_nl;
                LDSM_X4(b[p], bs + (uint32_t)(n*128) + (((uint32_t)(ks*32 + b_bc)) ^ xorv));
            }
            #pragma unroll
            for(int mi=0; mi<4; mi++)
                #pragma unroll
                for(int ni=0; ni<8; ni++)
                    MMA_F16(c[mi][ni], a[mi], b[ni>>1][(ni&1)*2], b[ni>>1][(ni&1)*2+1]);
        }
        if(PHASE==1 && (step&15)==15)
            epilogue1(blockIdx.z*EPC + (step>>4));
    }

    if(PHASE==2){
        __syncthreads();
        #pragma unroll
        for(int mi=0; mi<4; mi++){
            int r0 = m0 + wm*64 + mi*16 + gr;
            #pragma unroll
            for(int half=0; half<2; half++){
                int row = r0 + half*8;
                #pragma unroll
                for(int ni=0; ni<8; ni++){
                    int col = n0 + wn*64 + ni*8 + gc;
                    float2* p = (float2*)(dout + (size_t)row*DIM + col);
                    float2 o = *p;
                    o.x += c[mi][ni][half*2+0];
                    o.y += c[mi][ni][half*2+1];
                    *p = o;
                }
            }
        }
    }
}

// ---------------- launch ----------------
extern "C" void kernel_launch(void* const* d_in, const int* in_sizes, int n_in,
                              void* d_out, int out_size){
    const float* x  = (const float*)d_in[0];
    const float* W1 = (const float*)d_in[1];
    const float* b1 = (const float*)d_in[2];
    const float* W2 = (const float*)d_in[3];
    const float* b2 = (const float*)d_in[4];
    const float* Wg = (const float*)d_in[5];
    const float* bg = (const float*)d_in[6];
    float* out = (float*)d_out;

    cudaFuncSetAttribute(gemm_kernel<1>, cudaFuncAttributeMaxDynamicSharedMemorySize, SMEM_DYN);
    cudaFuncSetAttribute(gemm_kernel<2>, cudaFuncAttributeMaxDynamicSharedMemorySize, SMEM_DYN);

    gates_kernel<<<NTOK, 128>>>(x, Wg, bg);
    dim3 tg(32, 32, NSK), tb(32, 8);
    transpose_round_kernel<<<tg, tb>>>(W1, 0);
    transpose_round_kernel<<<tg, tb>>>(W2, 1);
    biasinit_kernel<<<dim3(NTOK/32, DIM/128), 256>>>(b2, out);
    gemm_kernel<1><<<dim3(NTOK/BM, DIM/BN, NSK/EPC), 256, SMEM_DYN>>>(b1, nullptr);
    gemm_kernel<2><<<dim3(NTOK/BM, DIM/BN), 256, SMEM_DYN>>>(nullptr, out);
}

// round 7
// speedup vs baseline: 1.0555x; 1.0555x over previous
#include <cuda_runtime.h>
#include <cuda_fp16.h>
#include <cstdint>

#define DIM  1024
#define NTOK 4096
#define NSK  50
#define BM 128
#define BN 256
#define BK 64                             // 64 halves = 128B row
#define NSTAGE 4
#define A_BYTES (BM*128)                  // 16KB per stage
#define B_BYTES (BN*128)                  // 32KB per stage
#define SMEM_DYN (NSTAGE*(A_BYTES+B_BYTES) + 1024)   // 197632

// ---------------- scratch (static device, allocation-free) ----------------
__device__ __half g_Xh [(size_t)NTOK*DIM];
__device__ __half g_W1h[(size_t)NSK*DIM*DIM];        // transposed: [e][h][d]
__device__ __half g_W2h[(size_t)NSK*DIM*DIM];        // transposed: [e][d][h]
__device__ __half g_Hh [(size_t)NSK*NTOK*DIM];       // gate-scaled hidden
__device__ float  g_gates[(size_t)NTOK*NSK];

// ---------------- helpers ----------------
__device__ __forceinline__ uint32_t smem_u32(const void* p){
    uint32_t a; asm("{ .reg .u64 t; cvta.to.shared.u64 t, %1; cvt.u32.u64 %0, t; }":"=r"(a):"l"(p)); return a;
}
__device__ __forceinline__ void cp_async16(uint32_t s, const void* gp){
    uint64_t g = __cvta_generic_to_global(gp);
    asm volatile("cp.async.cg.shared.global [%0], [%1], 16;"::"r"(s),"l"(g));
}
#define CP_COMMIT() asm volatile("cp.async.commit_group;":::"memory")

#define LDSM_X4(r, a) \
    asm volatile("ldmatrix.sync.aligned.m8n8.x4.shared.b16 {%0,%1,%2,%3}, [%4];" \
        : "=r"((r)[0]),"=r"((r)[1]),"=r"((r)[2]),"=r"((r)[3]) : "r"(a))

#define MMA_F16(c, a, b0, b1) \
    asm volatile("mma.sync.aligned.m16n8k16.row.col.f32.f16.f16.f32 " \
        "{%0,%1,%2,%3},{%4,%5,%6,%7},{%8,%9},{%0,%1,%2,%3};" \
        : "+f"((c)[0]),"+f"((c)[1]),"+f"((c)[2]),"+f"((c)[3]) \
        : "r"((a)[0]),"r"((a)[1]),"r"((a)[2]),"r"((a)[3]),"r"(b0),"r"(b1))

// ---------------- prep kernels ----------------
// gates + x half-conversion fused (both read the same x row)
__global__ void gates_kernel(const float* __restrict__ x, const float* __restrict__ Wg,
                             const float* __restrict__ bg){
    int n = blockIdx.x, tid = threadIdx.x;
    __shared__ float xs[DIM]; __shared__ float raw[64]; __shared__ float ssum;
    for(int j=tid; j<DIM; j+=128){
        float v = x[(size_t)n*DIM + j];
        xs[j] = v;
        g_Xh[(size_t)n*DIM + j] = __float2half_rn(v);
    }
    __syncthreads();
    int wid = tid>>5, lid = tid&31;
    for(int s=wid; s<NSK; s+=4){
        float acc = 0.f;
        for(int j=lid; j<DIM; j+=32) acc += xs[j]*Wg[(size_t)j*NSK + s];
        #pragma unroll
        for(int o=16;o;o>>=1) acc += __shfl_xor_sync(0xFFFFFFFFu, acc, o);
        if(lid==0) raw[s] = acc + bg[s];
    }
    __syncthreads();
    if(tid==0){
        float m = -1e30f;
        for(int s=0;s<NSK;s++) m = fmaxf(m, raw[s]);
        float sm = 0.f;
        for(int s=0;s<NSK;s++){ float e = __expf(raw[s]-m); raw[s]=e; sm+=e; }
        ssum = sm;
    }
    __syncthreads();
    if(tid<NSK) g_gates[(size_t)n*NSK + tid] = raw[tid]/ssum;
}

// Fused transpose+convert for both weights, 64x64 tiles (128B fp16 write segments).
// z < NSK: W1 -> g_W1h ;  z >= NSK: W2 -> g_W2h.  out[e][j][i] = half(in[e][i][j])
__global__ void transpose_round_kernel(const float* __restrict__ W1,
                                       const float* __restrict__ W2){
    __shared__ float tile[64][65];
    int z = blockIdx.z;
    const float* in = (z < NSK) ? W1 : W2;
    __half* out = (z < NSK) ? g_W1h : g_W2h;
    int e = (z < NSK) ? z : z - NSK;
    size_t base = (size_t)e*DIM*DIM;
    int i0 = blockIdx.y*64, j0 = blockIdx.x*64;
    int tx = threadIdx.x & 63, ty = threadIdx.x >> 6;   // 256 threads: 64 x 4
    #pragma unroll
    for(int r=ty; r<64; r+=4)
        tile[r][tx] = in[base + (size_t)(i0+r)*DIM + j0 + tx];
    __syncthreads();
    #pragma unroll
    for(int r=ty; r<64; r+=4)
        out[base + (size_t)(j0+r)*DIM + i0 + tx] = __float2half_rn(tile[tx][r]);
}

// ---------------- main fp16 mma.sync GEMM ----------------
// 8 warps, warp grid 2x4, warp tile 64x64.
// PHASE 1: Hh[e][m][h] = half( gates[m][e]*relu( Xh @ W1h[e]^T + b1[e] ) )  grid (32,4,50)
// PHASE 2: out[m][d] = sum_e g*b2 (prologue) + Hh_all @ W2h_all^T (K=51200)  grid (32,4)
template<int PHASE>
__global__ void __launch_bounds__(256,1) gemm_kernel(const float* __restrict__ b1,
                                                     const float* __restrict__ b2,
                                                     float* __restrict__ dout){
    extern __shared__ char dsm[];
    const uint32_t sb = (smem_u32(dsm) + 1023u) & ~1023u;
    const uint32_t A0 = sb, B0 = sb + NSTAGE*A_BYTES;
    const int tid = threadIdx.x, wid = tid>>5, lane = tid&31;
    const int wm = wid & 1, wn = wid >> 1;            // 2x4 warp grid
    const int m0 = blockIdx.x*BM, n0 = blockIdx.y*BN;
    const int NS = (PHASE==1) ? (DIM/BK) : (NSK*DIM/BK);   // 16 / 800

    // ldmatrix per-lane addressing (SW128: 16B chunk ^= (row&7)<<4)
    const int mat = lane>>3, rr = lane&7;
    const int a_rowl = (mat&1)*8 + rr;
    const int a_bc   = (mat>>1)*16;
    const int b_nl   = (mat>>1)*8 + rr;
    const int b_bc   = (mat&1)*16;
    const uint32_t xorv = (uint32_t)(rr<<4);
    const int gr = lane>>2, gc = (lane&3)*2;

    float c[4][8][4];
    #pragma unroll
    for(int i=0;i<4;i++)
      #pragma unroll
      for(int j=0;j<8;j++)
        #pragma unroll
        for(int k=0;k<4;k++) c[i][j][k] = 0.f;

    auto load_tile = [&](int step){
        const __half *Ag, *Bg;
        if(PHASE==1){
            int e = blockIdx.z, kk = step*BK;
            Ag = g_Xh  + (size_t)m0*DIM + kk;
            Bg = g_W1h + ((size_t)e*DIM + n0)*DIM + kk;
        } else {
            int e = step>>4, kk = (step&15)*BK;
            Ag = g_Hh  + ((size_t)e*NTOK + m0)*DIM + kk;
            Bg = g_W2h + ((size_t)e*DIM + n0)*DIM + kk;
        }
        uint32_t as = A0 + (step&3)*A_BYTES, bs = B0 + (step&3)*B_BYTES;
        #pragma unroll
        for(int i=0;i<4;i++){ int q = tid + i*256; int r=q>>3, cc=q&7;
            cp_async16(as + (uint32_t)(r*128 + ((cc*16) ^ ((r&7)<<4))), Ag + (size_t)r*DIM + cc*8); }
        #pragma unroll
        for(int i=0;i<8;i++){ int q = tid + i*256; int r=q>>3, cc=q&7;
            cp_async16(bs + (uint32_t)(r*128 + ((cc*16) ^ ((r&7)<<4))), Bg + (size_t)r*DIM + cc*8); }
        CP_COMMIT();
    };

    load_tile(0); load_tile(1); load_tile(2);

    // PHASE 2 prologue (overlapped with pipeline fill): c = sum_e gates*b2
    if(PHASE==2){
        for(int e=0; e<NSK; e++){
            float gg[4][2];
            #pragma unroll
            for(int mi=0; mi<4; mi++)
                #pragma unroll
                for(int half=0; half<2; half++)
                    gg[mi][half] = g_gates[(size_t)(m0 + wm*64 + mi*16 + gr + half*8)*NSK + e];
            #pragma unroll
            for(int ni=0; ni<8; ni++){
                const float2 bb = *(const float2*)(b2 + (size_t)e*DIM + n0 + wn*64 + ni*8 + gc);
                #pragma unroll
                for(int mi=0; mi<4; mi++)
                    #pragma unroll
                    for(int half=0; half<2; half++){
                        c[mi][ni][half*2+0] += gg[mi][half]*bb.x;
                        c[mi][ni][half*2+1] += gg[mi][half]*bb.y;
                    }
            }
        }
    }

    for(int step=0; step<NS; step++){
        asm volatile("cp.async.wait_group 2;":::"memory");
        __syncthreads();
        if(step+3 < NS) load_tile(step+3); else CP_COMMIT();

        const uint32_t as = A0 + (step&3)*A_BYTES;
        const uint32_t bs = B0 + (step&3)*B_BYTES;
        #pragma unroll
        for(int ks=0; ks<4; ks++){
            uint32_t a[4][4], b[4][4];
            #pragma unroll
            for(int mi=0; mi<4; mi++){
                int row = wm*64 + mi*16 + a_rowl;
                LDSM_X4(a[mi], as + (uint32_t)(row*128) + (((uint32_t)(ks*32 + a_bc)) ^ xorv));
            }
            #pragma unroll
            for(int p=0; p<4; p++){
                int n = wn*64 + p*16 + b_nl;
                LDSM_X4(b[p], bs + (uint32_t)(n*128) + (((uint32_t)(ks*32 + b_bc)) ^ xorv));
            }
            #pragma unroll
            for(int mi=0; mi<4; mi++)
                #pragma unroll
                for(int ni=0; ni<8; ni++)
                    MMA_F16(c[mi][ni], a[mi], b[ni>>1][(ni&1)*2], b[ni>>1][(ni&1)*2+1]);
        }
    }
    __syncthreads();

    // ---------------- epilogue ----------------
    #pragma unroll
    for(int mi=0; mi<4; mi++){
        int r0 = m0 + wm*64 + mi*16 + gr;
        #pragma unroll
        for(int half=0; half<2; half++){
            int row = r0 + half*8;
            float gate = 0.f;
            if(PHASE==1) gate = g_gates[(size_t)row*NSK + blockIdx.z];
            #pragma unroll
            for(int ni=0; ni<8; ni++){
                int col = n0 + wn*64 + ni*8 + gc;
                float v0 = c[mi][ni][half*2+0];
                float v1 = c[mi][ni][half*2+1];
                if(PHASE==1){
                    const float2 bb = *(const float2*)(b1 + (size_t)blockIdx.z*DIM + col);
                    float o0 = fmaxf(v0 + bb.x, 0.f)*gate;
                    float o1 = fmaxf(v1 + bb.y, 0.f)*gate;
                    *(__half2*)(g_Hh + ((size_t)blockIdx.z*NTOK + row)*DIM + col) =
                        __floats2half2_rn(o0, o1);
                } else {
                    *(float2*)(dout + (size_t)row*DIM + col) = make_float2(v0, v1);
                }
            }
        }
    }
}

// ---------------- launch ----------------
extern "C" void kernel_launch(void* const* d_in, const int* in_sizes, int n_in,
                              void* d_out, int out_size){
    const float* x  = (const float*)d_in[0];
    const float* W1 = (const float*)d_in[1];
    const float* b1 = (const float*)d_in[2];
    const float* W2 = (const float*)d_in[3];
    const float* b2 = (const float*)d_in[4];
    const float* Wg = (const float*)d_in[5];
    const float* bg = (const float*)d_in[6];
    float* out = (float*)d_out;

    cudaFuncSetAttribute(gemm_kernel<1>, cudaFuncAttributeMaxDynamicSharedMemorySize, SMEM_DYN);
    cudaFuncSetAttribute(gemm_kernel<2>, cudaFuncAttributeMaxDynamicSharedMemorySize, SMEM_DYN);

    gates_kernel<<<NTOK, 128>>>(x, Wg, bg);
    transpose_round_kernel<<<dim3(16, 16, 2*NSK), 256>>>(W1, W2);
    gemm_kernel<1><<<dim3(NTOK/BM, DIM/BN, NSK), 256, SMEM_DYN>>>(b1, nullptr, nullptr);
    gemm_kernel<2><<<dim3(NTOK/BM, DIM/BN), 256, SMEM_DYN>>>(nullptr, b2, out);
}

// round 8
// speedup vs baseline: 1.2829x; 1.2154x over previous
#include <cuda_runtime.h>
#include <cuda_fp16.h>
#include <cstdint>

#define DIM  1024
#define NTOK 4096
#define NSK  50
#define BM 128
#define BN 256
#define BK 64                             // 64 halves = 128B (A) / 64 k-rows (B)
#define NSTAGE 4
#define A_BYTES (BM*128)                  // 16KB per stage: 128 m-rows x 128B
#define B_BYTES (BK*512)                  // 32KB per stage: 64 k-rows x 512B
#define SMEM_DYN (NSTAGE*(A_BYTES+B_BYTES) + 1024)   // 197632

// ---------------- scratch (static device, allocation-free) ----------------
__device__ __half g_Xh [(size_t)NTOK*DIM];
__device__ __half g_W1h[(size_t)NSK*DIM*DIM];        // original layout [e][d][h]
__device__ __half g_W2h[(size_t)NSK*DIM*DIM];        // original layout [e][h][d]
__device__ __half g_Hh [(size_t)NSK*NTOK*DIM];       // gate-scaled hidden [e][m][h]
__device__ float  g_gates[(size_t)NTOK*NSK];
__device__ float  g_Wgt[64*DIM];                      // transposed gate weights [s][j]

// ---------------- helpers ----------------
__device__ __forceinline__ uint32_t smem_u32(const void* p){
    uint32_t a; asm("{ .reg .u64 t; cvta.to.shared.u64 t, %1; cvt.u32.u64 %0, t; }":"=r"(a):"l"(p)); return a;
}
__device__ __forceinline__ void cp_async16(uint32_t s, const void* gp){
    uint64_t g = __cvta_generic_to_global(gp);
    asm volatile("cp.async.cg.shared.global [%0], [%1], 16;"::"r"(s),"l"(g));
}
#define CP_COMMIT() asm volatile("cp.async.commit_group;":::"memory")

#define LDSM_X4(r, a) \
    asm volatile("ldmatrix.sync.aligned.m8n8.x4.shared.b16 {%0,%1,%2,%3}, [%4];" \
        : "=r"((r)[0]),"=r"((r)[1]),"=r"((r)[2]),"=r"((r)[3]) : "r"(a))

#define LDSM_X4_T(r, a) \
    asm volatile("ldmatrix.sync.aligned.m8n8.x4.trans.shared.b16 {%0,%1,%2,%3}, [%4];" \
        : "=r"((r)[0]),"=r"((r)[1]),"=r"((r)[2]),"=r"((r)[3]) : "r"(a))

#define MMA_F16(c, a, b0, b1) \
    asm volatile("mma.sync.aligned.m16n8k16.row.col.f32.f16.f16.f32 " \
        "{%0,%1,%2,%3},{%4,%5,%6,%7},{%8,%9},{%0,%1,%2,%3};" \
        : "+f"((c)[0]),"+f"((c)[1]),"+f"((c)[2]),"+f"((c)[3]) \
        : "r"((a)[0]),"r"((a)[1]),"r"((a)[2]),"r"((a)[3]),"r"(b0),"r"(b1))

// ---------------- prep kernels ----------------
// Wgt[s][j] = Wg[j][s]  (tiny: 1024x50)
__global__ void wg_transpose_kernel(const float* __restrict__ Wg){
    __shared__ float t[32][33];
    int j0 = blockIdx.x*32, s0 = blockIdx.y*32;
    int tx = threadIdx.x, ty = threadIdx.y;
    #pragma unroll
    for(int r=ty; r<32; r+=8)
        t[r][tx] = (s0+tx < NSK) ? Wg[(size_t)(j0+r)*NSK + s0+tx] : 0.f;
    __syncthreads();
    #pragma unroll
    for(int r=ty; r<32; r+=8)
        if(s0+r < NSK) g_Wgt[(size_t)(s0+r)*DIM + j0+tx] = t[tx][r];
}

// straight elementwise fp32 -> fp16 convert of both weight tensors
__global__ void convert_w_kernel(const float* __restrict__ W1, const float* __restrict__ W2){
    const float* src = blockIdx.y ? W2 : W1;
    __half* dst = blockIdx.y ? g_W2h : g_W1h;
    size_t base = (size_t)blockIdx.x*2048 + (size_t)threadIdx.x*8;
    float4 a = *(const float4*)(src + base);
    float4 b = *(const float4*)(src + base + 4);
    __half2 h[4];
    h[0] = __floats2half2_rn(a.x, a.y); h[1] = __floats2half2_rn(a.z, a.w);
    h[2] = __floats2half2_rn(b.x, b.y); h[3] = __floats2half2_rn(b.z, b.w);
    *(uint4*)(dst + base) = *(uint4*)h;
}

// gates + x half-conversion fused; Wgt reads are coalesced + L1-resident
__global__ void gates_kernel(const float* __restrict__ x, const float* __restrict__ bg){
    int n = blockIdx.x, tid = threadIdx.x;
    __shared__ float xs[DIM]; __shared__ float raw[64]; __shared__ float ssum;
    for(int j=tid; j<DIM; j+=128){
        float v = x[(size_t)n*DIM + j];
        xs[j] = v;
        g_Xh[(size_t)n*DIM + j] = __float2half_rn(v);
    }
    __syncthreads();
    int wid = tid>>5, lid = tid&31;
    for(int s=wid; s<NSK; s+=4){
        float acc = 0.f;
        #pragma unroll 8
        for(int j=lid; j<DIM; j+=32) acc += xs[j]*g_Wgt[(size_t)s*DIM + j];
        #pragma unroll
        for(int o=16;o;o>>=1) acc += __shfl_xor_sync(0xFFFFFFFFu, acc, o);
        if(lid==0) raw[s] = acc + bg[s];
    }
    __syncthreads();
    if(tid==0){
        float m = -1e30f;
        for(int s=0;s<NSK;s++) m = fmaxf(m, raw[s]);
        float sm = 0.f;
        for(int s=0;s<NSK;s++){ float e = __expf(raw[s]-m); raw[s]=e; sm+=e; }
        ssum = sm;
    }
    __syncthreads();
    if(tid<NSK) g_gates[(size_t)n*NSK + tid] = raw[tid]/ssum;
}

// ---------------- main fp16 mma.sync GEMM ----------------
// 8 warps, warp grid 2x4, warp tile 64x64. A row-major (non-trans ldmatrix),
// B row-major [k][n] loaded with ldmatrix.trans — weights used in ORIGINAL layout.
// PHASE 1: Hh[e][m][h] = half( gates[m][e]*relu( Xh @ W1[e] + b1[e] ) )  grid (32,4,50)
// PHASE 2: out[m][d] = sum_e g*b2 (prologue) + Hh_all @ W2_all (K=51200)  grid (32,4)
template<int PHASE>
__global__ void __launch_bounds__(256,1) gemm_kernel(const float* __restrict__ b1,
                                                     const float* __restrict__ b2,
                                                     float* __restrict__ dout){
    extern __shared__ char dsm[];
    const uint32_t sb = (smem_u32(dsm) + 1023u) & ~1023u;
    const uint32_t A0 = sb, B0 = sb + NSTAGE*A_BYTES;
    const int tid = threadIdx.x, wid = tid>>5, lane = tid&31;
    const int wm = wid & 1, wn = wid >> 1;            // 2x4 warp grid
    const int m0 = blockIdx.x*BM, n0 = blockIdx.y*BN;
    const int NS = (PHASE==1) ? (DIM/BK) : (NSK*DIM/BK);   // 16 / 800

    // A ldmatrix lanes (SW128 on 128B rows): 16B chunk ^= (row&7)<<4
    const int mat = lane>>3, rr = lane&7;
    const int a_rowl = (mat&1)*8 + rr;
    const int a_bc   = (mat>>1)*16;
    const uint32_t xorv = (uint32_t)(rr<<4);
    // B trans-ldmatrix lanes: rows are k (512B pitch), lanes 0-15 -> k0-15, 16-31 -> n+8
    const int b_row  = lane & 15;
    const int b_noff = (lane >> 4) * 16;   // byte offset selecting n8 block
    const int gr = lane>>2, gc = (lane&3)*2;

    float c[4][8][4];
    #pragma unroll
    for(int i=0;i<4;i++)
      #pragma unroll
      for(int j=0;j<8;j++)
        #pragma unroll
        for(int k=0;k<4;k++) c[i][j][k] = 0.f;

    auto load_tile = [&](int step){
        const __half *Ag, *Bg;
        if(PHASE==1){
            int e = blockIdx.z, kk = step*BK;
            Ag = g_Xh  + (size_t)m0*DIM + kk;
            Bg = g_W1h + (size_t)e*DIM*DIM + (size_t)kk*DIM + n0;
        } else {
            int e = step>>4, kk = (step&15)*BK;
            Ag = g_Hh  + ((size_t)e*NTOK + m0)*DIM + kk;
            Bg = g_W2h + (size_t)e*DIM*DIM + (size_t)kk*DIM + n0;
        }
        uint32_t as = A0 + (step&3)*A_BYTES, bs = B0 + (step&3)*B_BYTES;
        #pragma unroll
        for(int i=0;i<4;i++){ int q = tid + i*256; int r=q>>3, cc=q&7;
            cp_async16(as + (uint32_t)(r*128 + ((cc*16) ^ ((r&7)<<4))), Ag + (size_t)r*DIM + cc*8); }
        #pragma unroll
        for(int i=0;i<8;i++){ int q = tid + i*256; int r=q>>5, cc=q&31;
            cp_async16(bs + (uint32_t)(r*512 + ((cc*16) ^ ((r&7)<<4))), Bg + (size_t)r*DIM + cc*8); }
        CP_COMMIT();
    };

    load_tile(0); load_tile(1); load_tile(2);

    // PHASE 2 prologue (overlapped with pipeline fill): c = sum_e gates*b2
    if(PHASE==2){
        for(int e=0; e<NSK; e++){
            float gg[4][2];
            #pragma unroll
            for(int mi=0; mi<4; mi++)
                #pragma unroll
                for(int half=0; half<2; half++)
                    gg[mi][half] = g_gates[(size_t)(m0 + wm*64 + mi*16 + gr + half*8)*NSK + e];
            #pragma unroll
            for(int ni=0; ni<8; ni++){
                const float2 bb = *(const float2*)(b2 + (size_t)e*DIM + n0 + wn*64 + ni*8 + gc);
                #pragma unroll
                for(int mi=0; mi<4; mi++)
                    #pragma unroll
                    for(int half=0; half<2; half++){
                        c[mi][ni][half*2+0] += gg[mi][half]*bb.x;
                        c[mi][ni][half*2+1] += gg[mi][half]*bb.y;
                    }
            }
        }
    }

    for(int step=0; step<NS; step++){
        asm volatile("cp.async.wait_group 2;":::"memory");
        __syncthreads();
        if(step+3 < NS) load_tile(step+3); else CP_COMMIT();

        const uint32_t as = A0 + (step&3)*A_BYTES;
        const uint32_t bs = B0 + (step&3)*B_BYTES;
        #pragma unroll
        for(int ks=0; ks<4; ks++){      // 4 k16 slices per BK=64
            uint32_t a[4][4], b[4][4];
            #pragma unroll
            for(int mi=0; mi<4; mi++){
                int row = wm*64 + mi*16 + a_rowl;
                LDSM_X4(a[mi], as + (uint32_t)(row*128) + (((uint32_t)(ks*32 + a_bc)) ^ xorv));
            }
            #pragma unroll
            for(int p=0; p<4; p++){
                int rowk = ks*16 + b_row;
                uint32_t bcol = (uint32_t)(wn*128 + p*32 + b_noff);
                LDSM_X4_T(b[p], bs + (uint32_t)(rowk*512) + (bcol ^ (uint32_t)((rowk&7)<<4)));
            }
            #pragma unroll
            for(int mi=0; mi<4; mi++)
                #pragma unroll
                for(int ni=0; ni<8; ni++)
                    MMA_F16(c[mi][ni], a[mi], b[ni>>1][(ni&1)*2], b[ni>>1][(ni&1)*2+1]);
        }
    }
    __syncthreads();

    // ---------------- epilogue ----------------
    #pragma unroll
    for(int mi=0; mi<4; mi++){
        int r0 = m0 + wm*64 + mi*16 + gr;
        #pragma unroll
        for(int half=0; half<2; half++){
            int row = r0 + half*8;
            float gate = 0.f;
            if(PHASE==1) gate = g_gates[(size_t)row*NSK + blockIdx.z];
            #pragma unroll
            for(int ni=0; ni<8; ni++){
                int col = n0 + wn*64 + ni*8 + gc;
                float v0 = c[mi][ni][half*2+0];
                float v1 = c[mi][ni][half*2+1];
                if(PHASE==1){
                    const float2 bb = *(const float2*)(b1 + (size_t)blockIdx.z*DIM + col);
                    float o0 = fmaxf(v0 + bb.x, 0.f)*gate;
                    float o1 = fmaxf(v1 + bb.y, 0.f)*gate;
                    *(__half2*)(g_Hh + ((size_t)blockIdx.z*NTOK + row)*DIM + col) =
                        __floats2half2_rn(o0, o1);
                } else {
                    *(float2*)(dout + (size_t)row*DIM + col) = make_float2(v0, v1);
                }
            }
        }
    }
}

// ---------------- launch ----------------
extern "C" void kernel_launch(void* const* d_in, const int* in_sizes, int n_in,
                              void* d_out, int out_size){
    const float* x  = (const float*)d_in[0];
    const float* W1 = (const float*)d_in[1];
    const float* b1 = (const float*)d_in[2];
    const float* W2 = (const float*)d_in[3];
    const float* b2 = (const float*)d_in[4];
    const float* Wg = (const float*)d_in[5];
    const float* bg = (const float*)d_in[6];
    float* out = (float*)d_out;

    cudaFuncSetAttribute(gemm_kernel<1>, cudaFuncAttributeMaxDynamicSharedMemorySize, SMEM_DYN);
    cudaFuncSetAttribute(gemm_kernel<2>, cudaFuncAttributeMaxDynamicSharedMemorySize, SMEM_DYN);

    wg_transpose_kernel<<<dim3(32, 2), dim3(32, 8)>>>(Wg);
    gates_kernel<<<NTOK, 128>>>(x, bg);
    convert_w_kernel<<<dim3(25600, 2), 256>>>(W1, W2);
    gemm_kernel<1><<<dim3(NTOK/BM, DIM/BN, NSK), 256, SMEM_DYN>>>(b1, nullptr, nullptr);
    gemm_kernel<2><<<dim3(NTOK/BM, DIM/BN), 256, SMEM_DYN>>>(nullptr, b2, out);
}